// round 9
// baseline (speedup 1.0000x reference)
#include <cuda_runtime.h>
#include <stdint.h>

#define NB 4096
#define ND 256
#define NM 60
#define TILE 128
#define NT (NB / TILE)              // 32
#define NPAIR (NT * (NT + 1) / 2)   // 528
#define RSTRIDE 36                  // smem row stride in words (128B data + 16B pad)

// Device scratch (allocation-free). uint4-typed => 16B alignment.
__device__ uint4  g_q4[NB * 16];    // int8 quantized reps, row-major [NB][256B]
__device__ float  g_scale[NB];      // per-row dequant scale = rowmax/127
__device__ uint4  g_mask[NB];
__device__ int    g_cnt[NB];
__device__ float4 g_part4[NPAIR];

// ---------------------------------------------------------------------------
// Fast exp: FMA-only. rel err ~1.5e-7 on |s| <= ~11.  (numerics: UNCHANGED)
// ---------------------------------------------------------------------------
__device__ __forceinline__ float fexp(float s) {
    const float LOG2E = 1.4426950408889634f;
    const float MAGIC = 12582912.0f;             // 1.5 * 2^23
    float t  = s * LOG2E;
    float r  = fmaf(s, LOG2E, MAGIC);
    int   ei = __float_as_int(r) - 0x4B400000;
    float f  = t - (r - MAGIC);
    float z  = f * 0.6931471805599453f;
    float p  = fmaf(z, fmaf(z, fmaf(z, fmaf(z, fmaf(z,
                 fmaf(z, 1.3888889e-3f, 8.3333333e-3f),
                 4.1666668e-2f), 1.6666667e-1f), 0.5f), 1.0f), 1.0f);
    return __int_as_float(__float_as_int(p) + (ei << 23));
}

// ---------------------------------------------------------------------------
// Prep: warp-per-row (R7-proven shape). Normalize, per-row int8 quantize
// (exact int32 dots downstream), pack, plus mask/count (unchanged).
// ---------------------------------------------------------------------------
__global__ void __launch_bounds__(256) k_prep(const float* __restrict__ rep,
                                              const long long* __restrict__ codes) {
    int w    = threadIdx.x >> 5;
    int lane = threadIdx.x & 31;
    int row  = blockIdx.x * 8 + w;

    const float4* rp = reinterpret_cast<const float4*>(rep + (size_t)row * ND);
    float4 x0 = rp[lane * 2];
    float4 x1 = rp[lane * 2 + 1];
    float ss = x0.x * x0.x + x0.y * x0.y + x0.z * x0.z + x0.w * x0.w
             + x1.x * x1.x + x1.y * x1.y + x1.z * x1.z + x1.w * x1.w;
    #pragma unroll
    for (int o = 16; o; o >>= 1) ss += __shfl_xor_sync(0xffffffffu, ss, o);
    float inv = rsqrtf(ss);

    float y[8] = { x0.x * inv, x0.y * inv, x0.z * inv, x0.w * inv,
                   x1.x * inv, x1.y * inv, x1.z * inv, x1.w * inv };
    float m = 0.0f;
    #pragma unroll
    for (int k = 0; k < 8; k++) m = fmaxf(m, fabsf(y[k]));
    #pragma unroll
    for (int o = 16; o; o >>= 1) m = fmaxf(m, __shfl_xor_sync(0xffffffffu, m, o));

    float qs = 127.0f / m;
    int q[8];
    #pragma unroll
    for (int k = 0; k < 8; k++) q[k] = __float2int_rn(y[k] * qs);
    uint32_t u0 = (q[0] & 0xff) | ((q[1] & 0xff) << 8)
                | ((q[2] & 0xff) << 16) | ((uint32_t)(q[3] & 0xff) << 24);
    uint32_t u1 = (q[4] & 0xff) | ((q[5] & 0xff) << 8)
                | ((q[6] & 0xff) << 16) | ((uint32_t)(q[7] & 0xff) << 24);
    reinterpret_cast<uint2*>(g_q4)[(size_t)row * 32 + lane] = make_uint2(u0, u1);
    if (lane == 0) g_scale[row] = m * (1.0f / 127.0f);

    // ---- mask path (unchanged) ----
    const long long* mc = codes + (size_t)row * NM;
    uint32_t m0 = 0, m1 = 0, m2 = 0, m3 = 0;
    {
        int c = (int)mc[lane];
        uint32_t b = 1u << (c & 31);
        int wd = c >> 5;
        if      (wd == 0) m0 |= b;
        else if (wd == 1) m1 |= b;
        else if (wd == 2) m2 |= b;
        else              m3 |= b;
    }
    if (lane < NM - 32) {
        int c = (int)mc[32 + lane];
        uint32_t b = 1u << (c & 31);
        int wd = c >> 5;
        if      (wd == 0) m0 |= b;
        else if (wd == 1) m1 |= b;
        else if (wd == 2) m2 |= b;
        else              m3 |= b;
    }
    #pragma unroll
    for (int o = 16; o; o >>= 1) {
        m0 |= __shfl_xor_sync(0xffffffffu, m0, o);
        m1 |= __shfl_xor_sync(0xffffffffu, m1, o);
        m2 |= __shfl_xor_sync(0xffffffffu, m2, o);
        m3 |= __shfl_xor_sync(0xffffffffu, m3, o);
    }
    if (lane == 0) {
        g_mask[row] = make_uint4(m0, m1, m2, m3);
        g_cnt[row]  = __popc(m0) + __popc(m1) + __popc(m2) + __popc(m3);
    }
}

// ---------------------------------------------------------------------------
// int8 mma helper (s8 in, s32 acc): m16n8k32. Same per-thread word layout
// as the proven fp16 m16n8k16 path (word = 4 bytes).
// ---------------------------------------------------------------------------
#define MMA4I(D, A, B0, B1)                                                  \
    asm volatile("mma.sync.aligned.m16n8k32.row.col.s32.s8.s8.s32 "          \
                 "{%0,%1,%2,%3},{%4,%5,%6,%7},{%8,%9},{%0,%1,%2,%3};\n"      \
                 : "+r"((D)[0]), "+r"((D)[1]), "+r"((D)[2]), "+r"((D)[3])    \
                 : "r"((A)[0]), "r"((A)[1]), "r"((A)[2]), "r"((A)[3]),       \
                   "r"(B0), "r"(B1))

#define PROC(S, MA, CA, MB, CB, EQ) do {                                     \
    int inter = __popc((MA).x & (MB).x) + __popc((MA).y & (MB).y) +          \
                __popc((MA).z & (MB).z) + __popc((MA).w & (MB).w);           \
    bool pos = (10 * inter > 3 * ((CA) + (CB) - inter)) && !(EQ);            \
    float s = (S);                                                           \
    float e = fexp(s);                                                       \
    if (pos) { scnt++; sps += s; spe += e; } else { sneg += e; }             \
} while (0)

// ---------------------------------------------------------------------------
// Main pass: one block per upper-tri 128x128 tile pair (R5/R7-proven
// structure). int8 smem staging (2 chunks of K=128 bytes), IMMA m16n8k32
// (half the tensor instructions of the fp16 path), dequant in epilogue.
// ---------------------------------------------------------------------------
__global__ void __launch_bounds__(256, 2) k_pair() {
    __shared__ uint32_t sA[TILE * RSTRIDE];   // 18432 B
    __shared__ uint32_t sB[TILE * RSTRIDE];   // 18432 B
    __shared__ uint4 smMA[TILE], smMB[TILE];
    __shared__ int   scA[TILE], scB[TILE];
    __shared__ float sIA[TILE], sIB[TILE];    // dequant scales
    __shared__ float red[32];

    int tid = threadIdx.x;

    // decode blockIdx -> (ti, tj), ti <= tj
    int p = blockIdx.x, ti = 0;
    while (p >= NT - ti) { p -= NT - ti; ti++; }
    int tj = ti + p;
    int i0 = ti * TILE, j0 = tj * TILE;
    bool diag = (ti == tj);

    if (tid < TILE) {
        smMA[tid] = g_mask[i0 + tid]; scA[tid] = g_cnt[i0 + tid];
        sIA[tid]  = g_scale[i0 + tid] * 10.0f;   // fold temperature into A scale
    } else {
        int q = tid - TILE;
        smMB[q] = g_mask[j0 + q]; scB[q] = g_cnt[j0 + q];
        sIB[q]  = g_scale[j0 + q];
    }

    int lane = tid & 31, w = tid >> 5;
    int wm = w & 3, wn = w >> 2;                 // warp grid: 4(M) x 2(N)
    int g = lane >> 2, tg = lane & 3;

    int acc[64];
    #pragma unroll
    for (int i = 0; i < 64; i++) acc[i] = 0;

    // K = 256 bytes = 2 chunks of 128 bytes (8 uint4 per row per chunk)
    #pragma unroll 1
    for (int kc = 0; kc < 2; kc++) {
        __syncthreads();                         // previous compute done (and masks on kc==0)
        #pragma unroll
        for (int r = 0; r < 4; r++) {
            int idx = tid + r * 256;             // 0..1023
            int row = idx >> 3, seg = idx & 7;
            uint4 va = g_q4[(size_t)(i0 + row) * 16 + kc * 8 + seg];
            uint4 vb = g_q4[(size_t)(j0 + row) * 16 + kc * 8 + seg];
            *reinterpret_cast<uint4*>(&sA[row * RSTRIDE + seg * 4]) = va;
            *reinterpret_cast<uint4*>(&sB[row * RSTRIDE + seg * 4]) = vb;
        }
        __syncthreads();

        #pragma unroll
        for (int kk = 0; kk < 4; kk++) {         // 4 k32 slices per chunk
            uint32_t a[2][4];
            #pragma unroll
            for (int mi = 0; mi < 2; mi++) {
                int rb = (wm * 32 + mi * 16 + g) * RSTRIDE + kk * 8 + tg;
                a[mi][0] = sA[rb];
                a[mi][1] = sA[rb + 8 * RSTRIDE];
                a[mi][2] = sA[rb + 4];
                a[mi][3] = sA[rb + 8 * RSTRIDE + 4];
            }
            #pragma unroll
            for (int nt = 0; nt < 8; nt++) {
                int rb = (wn * 64 + nt * 8 + g) * RSTRIDE + kk * 8 + tg;
                uint32_t b0 = sB[rb];
                uint32_t b1 = sB[rb + 4];
                MMA4I(acc + nt * 4,      a[0], b0, b1);
                MMA4I(acc + 32 + nt * 4, a[1], b0, b1);
            }
        }
    }

    // ---- epilogue: s = acc * (10*scaleA) * scaleB; Jaccard mask; fexp ----
    float sneg = 0.0f, spe = 0.0f, sps = 0.0f;
    int scnt = 0;

    #pragma unroll
    for (int mi = 0; mi < 2; mi++) {
        int rl0 = wm * 32 + mi * 16 + g;
        uint4 mA0 = smMA[rl0];     int cA0 = scA[rl0];     float fA0 = sIA[rl0];
        uint4 mA1 = smMA[rl0 + 8]; int cA1 = scA[rl0 + 8]; float fA1 = sIA[rl0 + 8];
        #pragma unroll
        for (int nt = 0; nt < 8; nt++) {
            int cl = wn * 64 + nt * 8 + tg * 2;
            uint4 mB0 = smMB[cl];     int cB0 = scB[cl];     float fB0 = sIB[cl];
            uint4 mB1 = smMB[cl + 1]; int cB1 = scB[cl + 1]; float fB1 = sIB[cl + 1];
            int* A4 = acc + mi * 32 + nt * 4;
            PROC((float)A4[0] * (fA0 * fB0), mA0, cA0, mB0, cB0, diag && (rl0 == cl));
            PROC((float)A4[1] * (fA0 * fB1), mA0, cA0, mB1, cB1, diag && (rl0 == cl + 1));
            PROC((float)A4[2] * (fA1 * fB0), mA1, cA1, mB0, cB0, diag && (rl0 + 8 == cl));
            PROC((float)A4[3] * (fA1 * fB1), mA1, cA1, mB1, cB1, diag && (rl0 + 8 == cl + 1));
        }
    }

    // block reduce (deterministic, no atomics)
    float v0 = sneg, v1 = spe, v2 = sps, v3 = (float)scnt;
    #pragma unroll
    for (int o = 16; o; o >>= 1) {
        v0 += __shfl_xor_sync(0xffffffffu, v0, o);
        v1 += __shfl_xor_sync(0xffffffffu, v1, o);
        v2 += __shfl_xor_sync(0xffffffffu, v2, o);
        v3 += __shfl_xor_sync(0xffffffffu, v3, o);
    }
    if (lane == 0) { red[w * 4 + 0] = v0; red[w * 4 + 1] = v1;
                     red[w * 4 + 2] = v2; red[w * 4 + 3] = v3; }
    __syncthreads();
    if (tid == 0) {
        float n = 0, pe = 0, ps = 0, pc = 0;
        #pragma unroll
        for (int i = 0; i < 8; i++) {
            n += red[i * 4 + 0]; pe += red[i * 4 + 1];
            ps += red[i * 4 + 2]; pc += red[i * 4 + 3];
        }
        float f = diag ? 1.0f : 2.0f;   // off-diag tiles stand for (i,j) and (j,i)
        g_part4[blockIdx.x] = make_float4(n * f, pe * f, ps * f, pc * f);
    }
}

// ---------------------------------------------------------------------------
// Final (UNCHANGED): single warp, shfl-only deterministic double reduction.
// loss = log(negsum) + pos_exp/(negsum*n_pos) - pos_s/n_pos
// ---------------------------------------------------------------------------
__global__ void k_final(float* __restrict__ out) {
    int t = threadIdx.x;   // 32
    double n = 0, pe = 0, ps = 0, pc = 0;
    for (int q = t; q < NPAIR; q += 32) {
        float4 v = g_part4[q];
        n += (double)v.x; pe += (double)v.y;
        ps += (double)v.z; pc += (double)v.w;
    }
    #pragma unroll
    for (int o = 16; o; o >>= 1) {
        n  += __shfl_xor_sync(0xffffffffu, n,  o);
        pe += __shfl_xor_sync(0xffffffffu, pe, o);
        ps += __shfl_xor_sync(0xffffffffu, ps, o);
        pc += __shfl_xor_sync(0xffffffffu, pc, o);
    }
    if (t == 0) {
        double loss = 0.0;
        if (pc > 0.0) loss = log(n) + pe / (n * pc) - ps / pc;
        out[0] = (float)loss;
    }
}

extern "C" void kernel_launch(void* const* d_in, const int* in_sizes, int n_in,
                              void* d_out, int out_size) {
    (void)in_sizes; (void)n_in; (void)out_size;
    const float*     rep   = (const float*)d_in[0];
    const long long* codes = (const long long*)d_in[1];
    // d_in[2] = labels: unused by the reference loss

    k_prep<<<NB / 8, 256>>>(rep, codes);
    k_pair<<<NPAIR, 256>>>();
    k_final<<<1, 32>>>((float*)d_out);
}

// round 10
// speedup vs baseline: 1.1849x; 1.1849x over previous
#include <cuda_runtime.h>
#include <cuda_fp16.h>
#include <stdint.h>

#define NB 4096
#define ND 256
#define NM 60
#define TILE 128
#define NT (NB / TILE)              // 32
#define NPAIR (NT * (NT + 1) / 2)   // 528
#define RSTRIDE 36                  // smem row stride in words (128B data + 16B pad)

// Device scratch (allocation-free). uint4-typed => 16B alignment.
__device__ uint4  g_norm4[NB * ND * 2 / 16];  // fp16 normalized reps, row-major [NB][ND]
__device__ uint4  g_mask[NB];
__device__ int    g_cnt[NB];
__device__ float4 g_part4[NPAIR];

// ---------------------------------------------------------------------------
// Fast exp: FMA-only. rel err ~1.5e-7 on |s| <= ~11.  (numerics: UNCHANGED)
// ---------------------------------------------------------------------------
__device__ __forceinline__ float fexp(float s) {
    const float LOG2E = 1.4426950408889634f;
    const float MAGIC = 12582912.0f;             // 1.5 * 2^23
    float t  = s * LOG2E;
    float r  = fmaf(s, LOG2E, MAGIC);
    int   ei = __float_as_int(r) - 0x4B400000;
    float f  = t - (r - MAGIC);
    float z  = f * 0.6931471805599453f;
    float p  = fmaf(z, fmaf(z, fmaf(z, fmaf(z, fmaf(z,
                 fmaf(z, 1.3888889e-3f, 8.3333333e-3f),
                 4.1666668e-2f), 1.6666667e-1f), 0.5f), 1.0f), 1.0f);
    return __int_as_float(__float_as_int(p) + (ei << 23));
}

// ---------------------------------------------------------------------------
// Prep (UNCHANGED from R7, proven 6us): warp-per-row normalize + mask.
// ---------------------------------------------------------------------------
__global__ void __launch_bounds__(256) k_prep(const float* __restrict__ rep,
                                              const long long* __restrict__ codes) {
    int w    = threadIdx.x >> 5;
    int lane = threadIdx.x & 31;
    int row  = blockIdx.x * 8 + w;

    const float4* rp = reinterpret_cast<const float4*>(rep + (size_t)row * ND);
    float4 x0 = rp[lane * 2];
    float4 x1 = rp[lane * 2 + 1];
    float ss = x0.x * x0.x + x0.y * x0.y + x0.z * x0.z + x0.w * x0.w
             + x1.x * x1.x + x1.y * x1.y + x1.z * x1.z + x1.w * x1.w;
    #pragma unroll
    for (int o = 16; o; o >>= 1) ss += __shfl_xor_sync(0xffffffffu, ss, o);
    float inv = rsqrtf(ss);

    __half2 h[4];
    h[0] = __floats2half2_rn(x0.x * inv, x0.y * inv);
    h[1] = __floats2half2_rn(x0.z * inv, x0.w * inv);
    h[2] = __floats2half2_rn(x1.x * inv, x1.y * inv);
    h[3] = __floats2half2_rn(x1.z * inv, x1.w * inv);
    g_norm4[(size_t)row * 32 + lane] = *reinterpret_cast<uint4*>(h);

    const long long* mc = codes + (size_t)row * NM;
    uint32_t m0 = 0, m1 = 0, m2 = 0, m3 = 0;
    {
        int c = (int)mc[lane];
        uint32_t b = 1u << (c & 31);
        int wd = c >> 5;
        if      (wd == 0) m0 |= b;
        else if (wd == 1) m1 |= b;
        else if (wd == 2) m2 |= b;
        else              m3 |= b;
    }
    if (lane < NM - 32) {
        int c = (int)mc[32 + lane];
        uint32_t b = 1u << (c & 31);
        int wd = c >> 5;
        if      (wd == 0) m0 |= b;
        else if (wd == 1) m1 |= b;
        else if (wd == 2) m2 |= b;
        else              m3 |= b;
    }
    #pragma unroll
    for (int o = 16; o; o >>= 1) {
        m0 |= __shfl_xor_sync(0xffffffffu, m0, o);
        m1 |= __shfl_xor_sync(0xffffffffu, m1, o);
        m2 |= __shfl_xor_sync(0xffffffffu, m2, o);
        m3 |= __shfl_xor_sync(0xffffffffu, m3, o);
    }
    if (lane == 0) {
        g_mask[row] = make_uint4(m0, m1, m2, m3);
        g_cnt[row]  = __popc(m0) + __popc(m1) + __popc(m2) + __popc(m3);
    }
}

// ---------------------------------------------------------------------------
// fp16 mma with fp16 ACCUMULATORS: D/C are 2 b32 regs = {c0,c1},{c2,c3} halves
// (same element->thread mapping as the f32-accum form, packed).
// ---------------------------------------------------------------------------
#define MMA2H(D0, D1, A, B0, B1)                                             \
    asm volatile("mma.sync.aligned.m16n8k16.row.col.f16.f16.f16.f16 "        \
                 "{%0,%1},{%2,%3,%4,%5},{%6,%7},{%0,%1};\n"                  \
                 : "+r"(D0), "+r"(D1)                                        \
                 : "r"((A)[0]), "r"((A)[1]), "r"((A)[2]), "r"((A)[3]),       \
                   "r"(B0), "r"(B1))

#define PROC(S, MA, CA, MB, CB, EQ) do {                                     \
    int inter = __popc((MA).x & (MB).x) + __popc((MA).y & (MB).y) +          \
                __popc((MA).z & (MB).z) + __popc((MA).w & (MB).w);           \
    bool pos = (10 * inter > 3 * ((CA) + (CB) - inter)) && !(EQ);            \
    float s = (S) * 10.0f;                                                   \
    float e = fexp(s);                                                       \
    if (pos) { scnt++; sps += s; spe += e; } else { sneg += e; }             \
} while (0)

// ---------------------------------------------------------------------------
// Main pass (R7 structure; f16 accumulators halve acc regs -> occupancy 3).
// One block per upper-tri 128x128 tile pair; smem staging; fused epilogue.
// ---------------------------------------------------------------------------
__global__ void __launch_bounds__(256, 3) k_pair() {
    __shared__ uint32_t sA[TILE * RSTRIDE];   // 18432 B
    __shared__ uint32_t sB[TILE * RSTRIDE];   // 18432 B
    __shared__ uint4 smMA[TILE], smMB[TILE];
    __shared__ int   scA[TILE], scB[TILE];
    __shared__ float red[32];

    int tid = threadIdx.x;

    // decode blockIdx -> (ti, tj), ti <= tj
    int p = blockIdx.x, ti = 0;
    while (p >= NT - ti) { p -= NT - ti; ti++; }
    int tj = ti + p;
    int i0 = ti * TILE, j0 = tj * TILE;
    bool diag = (ti == tj);

    if (tid < TILE) { smMA[tid] = g_mask[i0 + tid]; scA[tid] = g_cnt[i0 + tid]; }
    else { int q = tid - TILE; smMB[q] = g_mask[j0 + q]; scB[q] = g_cnt[j0 + q]; }

    int lane = tid & 31, w = tid >> 5;
    int wm = w & 3, wn = w >> 2;                 // warp grid: 4(M) x 2(N)
    int g = lane >> 2, tg = lane & 3;

    // f16 accumulators: [mi(2)][nt(8)][2 regs] -> 32 b32 regs
    uint32_t acc[32];
    #pragma unroll
    for (int i = 0; i < 32; i++) acc[i] = 0u;    // packed f16 zeros

    // K = 256 elems = 4 chunks of 64 elems (8 uint4 per row per chunk)
    #pragma unroll 1
    for (int kc = 0; kc < 4; kc++) {
        __syncthreads();                         // previous compute done (and masks on kc==0)
        #pragma unroll
        for (int r = 0; r < 4; r++) {
            int idx = tid + r * 256;             // 0..1023
            int row = idx >> 3, seg = idx & 7;
            uint4 va = g_norm4[(size_t)(i0 + row) * 32 + kc * 8 + seg];
            uint4 vb = g_norm4[(size_t)(j0 + row) * 32 + kc * 8 + seg];
            *reinterpret_cast<uint4*>(&sA[row * RSTRIDE + seg * 4]) = va;
            *reinterpret_cast<uint4*>(&sB[row * RSTRIDE + seg * 4]) = vb;
        }
        __syncthreads();

        #pragma unroll
        for (int kk = 0; kk < 4; kk++) {         // 4 k16 slices per chunk
            uint32_t a[2][4];
            #pragma unroll
            for (int mi = 0; mi < 2; mi++) {
                int rb = (wm * 32 + mi * 16 + g) * RSTRIDE + kk * 8 + tg;
                a[mi][0] = sA[rb];
                a[mi][1] = sA[rb + 8 * RSTRIDE];
                a[mi][2] = sA[rb + 4];
                a[mi][3] = sA[rb + 8 * RSTRIDE + 4];
            }
            #pragma unroll
            for (int nt = 0; nt < 8; nt++) {
                int rb = (wn * 64 + nt * 8 + g) * RSTRIDE + kk * 8 + tg;
                uint32_t b0 = sB[rb];
                uint32_t b1 = sB[rb + 4];
                MMA2H(acc[nt * 2],      acc[nt * 2 + 1],      a[0], b0, b1);
                MMA2H(acc[16 + nt * 2], acc[16 + nt * 2 + 1], a[1], b0, b1);
            }
        }
    }

    // ---- epilogue: unpack f16 pairs, Jaccard mask, fexp, accumulate ----
    float sneg = 0.0f, spe = 0.0f, sps = 0.0f;
    int scnt = 0;

    #pragma unroll
    for (int mi = 0; mi < 2; mi++) {
        int rl0 = wm * 32 + mi * 16 + g;
        uint4 mA0 = smMA[rl0];     int cA0 = scA[rl0];
        uint4 mA1 = smMA[rl0 + 8]; int cA1 = scA[rl0 + 8];
        #pragma unroll
        for (int nt = 0; nt < 8; nt++) {
            int cl = wn * 64 + nt * 8 + tg * 2;
            uint4 mB0 = smMB[cl];     int cB0 = scB[cl];
            uint4 mB1 = smMB[cl + 1]; int cB1 = scB[cl + 1];
            uint32_t d0 = acc[mi * 16 + nt * 2];       // {c0, c1} rows g
            uint32_t d1 = acc[mi * 16 + nt * 2 + 1];   // {c2, c3} rows g+8
            float2 f01 = __half22float2(*reinterpret_cast<__half2*>(&d0));
            float2 f23 = __half22float2(*reinterpret_cast<__half2*>(&d1));
            PROC(f01.x, mA0, cA0, mB0, cB0, diag && (rl0 == cl));
            PROC(f01.y, mA0, cA0, mB1, cB1, diag && (rl0 == cl + 1));
            PROC(f23.x, mA1, cA1, mB0, cB0, diag && (rl0 + 8 == cl));
            PROC(f23.y, mA1, cA1, mB1, cB1, diag && (rl0 + 8 == cl + 1));
        }
    }

    // block reduce (deterministic, no atomics)
    float v0 = sneg, v1 = spe, v2 = sps, v3 = (float)scnt;
    #pragma unroll
    for (int o = 16; o; o >>= 1) {
        v0 += __shfl_xor_sync(0xffffffffu, v0, o);
        v1 += __shfl_xor_sync(0xffffffffu, v1, o);
        v2 += __shfl_xor_sync(0xffffffffu, v2, o);
        v3 += __shfl_xor_sync(0xffffffffu, v3, o);
    }
    if (lane == 0) { red[w * 4 + 0] = v0; red[w * 4 + 1] = v1;
                     red[w * 4 + 2] = v2; red[w * 4 + 3] = v3; }
    __syncthreads();
    if (tid == 0) {
        float n = 0, pe = 0, ps = 0, pc = 0;
        #pragma unroll
        for (int i = 0; i < 8; i++) {
            n += red[i * 4 + 0]; pe += red[i * 4 + 1];
            ps += red[i * 4 + 2]; pc += red[i * 4 + 3];
        }
        float f = diag ? 1.0f : 2.0f;   // off-diag tiles stand for (i,j) and (j,i)
        g_part4[blockIdx.x] = make_float4(n * f, pe * f, ps * f, pc * f);
    }
}

// ---------------------------------------------------------------------------
// Final (UNCHANGED): single warp, shfl-only deterministic double reduction.
// loss = log(negsum) + pos_exp/(negsum*n_pos) - pos_s/n_pos
// ---------------------------------------------------------------------------
__global__ void k_final(float* __restrict__ out) {
    int t = threadIdx.x;   // 32
    double n = 0, pe = 0, ps = 0, pc = 0;
    for (int q = t; q < NPAIR; q += 32) {
        float4 v = g_part4[q];
        n += (double)v.x; pe += (double)v.y;
        ps += (double)v.z; pc += (double)v.w;
    }
    #pragma unroll
    for (int o = 16; o; o >>= 1) {
        n  += __shfl_xor_sync(0xffffffffu, n,  o);
        pe += __shfl_xor_sync(0xffffffffu, pe, o);
        ps += __shfl_xor_sync(0xffffffffu, ps, o);
        pc += __shfl_xor_sync(0xffffffffu, pc, o);
    }
    if (t == 0) {
        double loss = 0.0;
        if (pc > 0.0) loss = log(n) + pe / (n * pc) - ps / pc;
        out[0] = (float)loss;
    }
}

extern "C" void kernel_launch(void* const* d_in, const int* in_sizes, int n_in,
                              void* d_out, int out_size) {
    (void)in_sizes; (void)n_in; (void)out_size;
    const float*     rep   = (const float*)d_in[0];
    const long long* codes = (const long long*)d_in[1];
    // d_in[2] = labels: unused by the reference loss

    k_prep<<<NB / 8, 256>>>(rep, codes);
    k_pair<<<NPAIR, 256>>>();
    k_final<<<1, 32>>>((float*)d_out);
}

// round 11
// speedup vs baseline: 1.4038x; 1.1847x over previous
#include <cuda_runtime.h>
#include <cuda_fp16.h>
#include <stdint.h>

#define NB 4096
#define ND 256
#define NM 60
#define TILE 128
#define NT (NB / TILE)              // 32
#define NPAIR (NT * (NT + 1) / 2)   // 528
#define RSTRIDE 36                  // smem row stride in words (128B data + 16B pad)

// Device scratch (allocation-free). uint4-typed => 16B alignment.
__device__ uint4    g_norm4[NB * ND * 2 / 16]; // fp16 normalized reps [NB][ND]
__device__ uint4    g_mask[NB];
__device__ int      g_cnt[NB];
__device__ float4   g_part4[NPAIR];
__device__ unsigned g_ctr;                     // zero-init; reset by last block

// ---------------------------------------------------------------------------
// Fast exp: FMA-only. rel err ~1.5e-7 on |s| <= ~11.  (numerics: UNCHANGED)
// ---------------------------------------------------------------------------
__device__ __forceinline__ float fexp(float s) {
    const float LOG2E = 1.4426950408889634f;
    const float MAGIC = 12582912.0f;             // 1.5 * 2^23
    float t  = s * LOG2E;
    float r  = fmaf(s, LOG2E, MAGIC);
    int   ei = __float_as_int(r) - 0x4B400000;
    float f  = t - (r - MAGIC);
    float z  = f * 0.6931471805599453f;
    float p  = fmaf(z, fmaf(z, fmaf(z, fmaf(z, fmaf(z,
                 fmaf(z, 1.3888889e-3f, 8.3333333e-3f),
                 4.1666668e-2f), 1.6666667e-1f), 0.5f), 1.0f), 1.0f);
    return __int_as_float(__float_as_int(p) + (ei << 23));
}

// ---------------------------------------------------------------------------
// Prep (UNCHANGED from R7, proven 6us): warp-per-row normalize + mask.
// ---------------------------------------------------------------------------
__global__ void __launch_bounds__(256) k_prep(const float* __restrict__ rep,
                                              const long long* __restrict__ codes) {
    int w    = threadIdx.x >> 5;
    int lane = threadIdx.x & 31;
    int row  = blockIdx.x * 8 + w;
    if (blockIdx.x == 0 && threadIdx.x == 0) g_ctr = 0u;   // guard reset

    const float4* rp = reinterpret_cast<const float4*>(rep + (size_t)row * ND);
    float4 x0 = rp[lane * 2];
    float4 x1 = rp[lane * 2 + 1];
    float ss = x0.x * x0.x + x0.y * x0.y + x0.z * x0.z + x0.w * x0.w
             + x1.x * x1.x + x1.y * x1.y + x1.z * x1.z + x1.w * x1.w;
    #pragma unroll
    for (int o = 16; o; o >>= 1) ss += __shfl_xor_sync(0xffffffffu, ss, o);
    float inv = rsqrtf(ss);

    __half2 h[4];
    h[0] = __floats2half2_rn(x0.x * inv, x0.y * inv);
    h[1] = __floats2half2_rn(x0.z * inv, x0.w * inv);
    h[2] = __floats2half2_rn(x1.x * inv, x1.y * inv);
    h[3] = __floats2half2_rn(x1.z * inv, x1.w * inv);
    g_norm4[(size_t)row * 32 + lane] = *reinterpret_cast<uint4*>(h);

    const long long* mc = codes + (size_t)row * NM;
    uint32_t m0 = 0, m1 = 0, m2 = 0, m3 = 0;
    {
        int c = (int)mc[lane];
        uint32_t b = 1u << (c & 31);
        int wd = c >> 5;
        if      (wd == 0) m0 |= b;
        else if (wd == 1) m1 |= b;
        else if (wd == 2) m2 |= b;
        else              m3 |= b;
    }
    if (lane < NM - 32) {
        int c = (int)mc[32 + lane];
        uint32_t b = 1u << (c & 31);
        int wd = c >> 5;
        if      (wd == 0) m0 |= b;
        else if (wd == 1) m1 |= b;
        else if (wd == 2) m2 |= b;
        else              m3 |= b;
    }
    #pragma unroll
    for (int o = 16; o; o >>= 1) {
        m0 |= __shfl_xor_sync(0xffffffffu, m0, o);
        m1 |= __shfl_xor_sync(0xffffffffu, m1, o);
        m2 |= __shfl_xor_sync(0xffffffffu, m2, o);
        m3 |= __shfl_xor_sync(0xffffffffu, m3, o);
    }
    if (lane == 0) {
        g_mask[row] = make_uint4(m0, m1, m2, m3);
        g_cnt[row]  = __popc(m0) + __popc(m1) + __popc(m2) + __popc(m3);
    }
}

// ---------------------------------------------------------------------------
// mma helper (f16 in, f32 acc) — EXACT R7 instruction
// ---------------------------------------------------------------------------
#define MMA4(D, A, B0, B1)                                                   \
    asm volatile("mma.sync.aligned.m16n8k16.row.col.f32.f16.f16.f32 "        \
                 "{%0,%1,%2,%3},{%4,%5,%6,%7},{%8,%9},{%0,%1,%2,%3};\n"      \
                 : "+f"((D)[0]), "+f"((D)[1]), "+f"((D)[2]), "+f"((D)[3])    \
                 : "r"((A)[0]), "r"((A)[1]), "r"((A)[2]), "r"((A)[3]),       \
                   "r"(B0), "r"(B1))

#define PROC(ACC, MA, CA, MB, CB, EQ) do {                                   \
    int inter = __popc((MA).x & (MB).x) + __popc((MA).y & (MB).y) +          \
                __popc((MA).z & (MB).z) + __popc((MA).w & (MB).w);           \
    bool pos = (10 * inter > 3 * ((CA) + (CB) - inter)) && !(EQ);            \
    float s = (ACC) * 10.0f;                                                 \
    float e = fexp(s);                                                       \
    if (pos) { scnt++; sps += s; spe += e; } else { sneg += e; }             \
} while (0)

// ---------------------------------------------------------------------------
// Main pass (R7 MMA path + register-prefetch pipeline + fused last-block
// final reduction). One block per upper-tri 128x128 tile pair.
// ---------------------------------------------------------------------------
__global__ void __launch_bounds__(256, 2) k_pair(float* __restrict__ out) {
    __shared__ uint32_t sA[TILE * RSTRIDE];   // 18432 B
    __shared__ uint32_t sB[TILE * RSTRIDE];   // 18432 B
    __shared__ uint4 smMA[TILE], smMB[TILE];
    __shared__ int   scA[TILE], scB[TILE];
    __shared__ float red[32];
    __shared__ double sdd[32];
    __shared__ int   flag;

    int tid = threadIdx.x;

    // decode blockIdx -> (ti, tj), ti <= tj
    int p = blockIdx.x, ti = 0;
    while (p >= NT - ti) { p -= NT - ti; ti++; }
    int tj = ti + p;
    int i0 = ti * TILE, j0 = tj * TILE;
    bool diag = (ti == tj);

    if (tid < TILE) { smMA[tid] = g_mask[i0 + tid]; scA[tid] = g_cnt[i0 + tid]; }
    else { int q = tid - TILE; smMB[q] = g_mask[j0 + q]; scB[q] = g_cnt[j0 + q]; }

    int lane = tid & 31, w = tid >> 5;
    int wm = w & 3, wn = w >> 2;                 // warp grid: 4(M) x 2(N)
    int g = lane >> 2, tg = lane & 3;

    float acc[64];
    #pragma unroll
    for (int i = 0; i < 64; i++) acc[i] = 0.0f;

    // register prefetch buffers: chunk kc's data staged through regs
    uint4 pva[4], pvb[4];
    #pragma unroll
    for (int r = 0; r < 4; r++) {
        int idx = tid + r * 256;
        int row = idx >> 3, seg = idx & 7;
        pva[r] = g_norm4[(size_t)(i0 + row) * 32 + seg];
        pvb[r] = g_norm4[(size_t)(j0 + row) * 32 + seg];
    }

    // K = 256 elems = 4 chunks of 64 elems (8 uint4 per row per chunk)
    #pragma unroll 1
    for (int kc = 0; kc < 4; kc++) {
        __syncthreads();                         // previous compute done (and masks on kc==0)
        #pragma unroll
        for (int r = 0; r < 4; r++) {
            int idx = tid + r * 256;
            int row = idx >> 3, seg = idx & 7;
            *reinterpret_cast<uint4*>(&sA[row * RSTRIDE + seg * 4]) = pva[r];
            *reinterpret_cast<uint4*>(&sB[row * RSTRIDE + seg * 4]) = pvb[r];
        }
        __syncthreads();

        if (kc < 3) {                            // prefetch next chunk (hides LDG latency)
            #pragma unroll
            for (int r = 0; r < 4; r++) {
                int idx = tid + r * 256;
                int row = idx >> 3, seg = idx & 7;
                pva[r] = g_norm4[(size_t)(i0 + row) * 32 + (kc + 1) * 8 + seg];
                pvb[r] = g_norm4[(size_t)(j0 + row) * 32 + (kc + 1) * 8 + seg];
            }
        }

        #pragma unroll
        for (int kk = 0; kk < 4; kk++) {         // 4 k16 slices per chunk
            uint32_t a[2][4];
            #pragma unroll
            for (int mi = 0; mi < 2; mi++) {
                int rb = (wm * 32 + mi * 16 + g) * RSTRIDE + kk * 8 + tg;
                a[mi][0] = sA[rb];
                a[mi][1] = sA[rb + 8 * RSTRIDE];
                a[mi][2] = sA[rb + 4];
                a[mi][3] = sA[rb + 8 * RSTRIDE + 4];
            }
            #pragma unroll
            for (int nt = 0; nt < 8; nt++) {
                int rb = (wn * 64 + nt * 8 + g) * RSTRIDE + kk * 8 + tg;
                uint32_t b0 = sB[rb];
                uint32_t b1 = sB[rb + 4];
                MMA4(acc + nt * 4,      a[0], b0, b1);
                MMA4(acc + 32 + nt * 4, a[1], b0, b1);
            }
        }
    }

    // ---- epilogue (UNCHANGED numerics) ----
    float sneg = 0.0f, spe = 0.0f, sps = 0.0f;
    int scnt = 0;

    #pragma unroll
    for (int mi = 0; mi < 2; mi++) {
        int rl0 = wm * 32 + mi * 16 + g;
        uint4 mA0 = smMA[rl0];     int cA0 = scA[rl0];
        uint4 mA1 = smMA[rl0 + 8]; int cA1 = scA[rl0 + 8];
        #pragma unroll
        for (int nt = 0; nt < 8; nt++) {
            int cl = wn * 64 + nt * 8 + tg * 2;
            uint4 mB0 = smMB[cl];     int cB0 = scB[cl];
            uint4 mB1 = smMB[cl + 1]; int cB1 = scB[cl + 1];
            float* A4 = acc + mi * 32 + nt * 4;
            PROC(A4[0], mA0, cA0, mB0, cB0, diag && (rl0 == cl));
            PROC(A4[1], mA0, cA0, mB1, cB1, diag && (rl0 == cl + 1));
            PROC(A4[2], mA1, cA1, mB0, cB0, diag && (rl0 + 8 == cl));
            PROC(A4[3], mA1, cA1, mB1, cB1, diag && (rl0 + 8 == cl + 1));
        }
    }

    // block reduce (deterministic, no atomics in the sums)
    float v0 = sneg, v1 = spe, v2 = sps, v3 = (float)scnt;
    #pragma unroll
    for (int o = 16; o; o >>= 1) {
        v0 += __shfl_xor_sync(0xffffffffu, v0, o);
        v1 += __shfl_xor_sync(0xffffffffu, v1, o);
        v2 += __shfl_xor_sync(0xffffffffu, v2, o);
        v3 += __shfl_xor_sync(0xffffffffu, v3, o);
    }
    if (lane == 0) { red[w * 4 + 0] = v0; red[w * 4 + 1] = v1;
                     red[w * 4 + 2] = v2; red[w * 4 + 3] = v3; }
    __syncthreads();
    if (tid == 0) {
        float n = 0, pe = 0, ps = 0, pc = 0;
        #pragma unroll
        for (int i = 0; i < 8; i++) {
            n += red[i * 4 + 0]; pe += red[i * 4 + 1];
            ps += red[i * 4 + 2]; pc += red[i * 4 + 3];
        }
        float f = diag ? 1.0f : 2.0f;   // off-diag tiles stand for (i,j) and (j,i)
        g_part4[blockIdx.x] = make_float4(n * f, pe * f, ps * f, pc * f);
        __threadfence();                 // publish partial before counting
        unsigned v = atomicAdd(&g_ctr, 1u);
        flag = (v == NPAIR - 1) ? 1 : 0;
    }
    __syncthreads();
    if (!flag) return;

    // ---- last block: deterministic double-precision final reduction ----
    __threadfence();                     // order reads after the atomic
    if (tid == 0) g_ctr = 0u;            // reset for next graph replay
    double n = 0, pe = 0, ps = 0, pc = 0;
    for (int q = tid; q < NPAIR; q += 256) {
        float4 v = __ldcg(&g_part4[q]);
        n += (double)v.x; pe += (double)v.y;
        ps += (double)v.z; pc += (double)v.w;
    }
    #pragma unroll
    for (int o = 16; o; o >>= 1) {
        n  += __shfl_xor_sync(0xffffffffu, n,  o);
        pe += __shfl_xor_sync(0xffffffffu, pe, o);
        ps += __shfl_xor_sync(0xffffffffu, ps, o);
        pc += __shfl_xor_sync(0xffffffffu, pc, o);
    }
    if (lane == 0) { sdd[w * 4 + 0] = n; sdd[w * 4 + 1] = pe;
                     sdd[w * 4 + 2] = ps; sdd[w * 4 + 3] = pc; }
    __syncthreads();
    if (tid == 0) {
        double N = 0, PE = 0, PS = 0, PC = 0;
        #pragma unroll
        for (int i = 0; i < 8; i++) {
            N += sdd[i * 4 + 0]; PE += sdd[i * 4 + 1];
            PS += sdd[i * 4 + 2]; PC += sdd[i * 4 + 3];
        }
        double loss = 0.0;
        if (PC > 0.0) loss = log(N) + PE / (N * PC) - PS / PC;
        out[0] = (float)loss;
    }
}

extern "C" void kernel_launch(void* const* d_in, const int* in_sizes, int n_in,
                              void* d_out, int out_size) {
    (void)in_sizes; (void)n_in; (void)out_size;
    const float*     rep   = (const float*)d_in[0];
    const long long* codes = (const long long*)d_in[1];
    // d_in[2] = labels: unused by the reference loss

    k_prep<<<NB / 8, 256>>>(rep, codes);
    k_pair<<<NPAIR, 256>>>((float*)d_out);
}